// round 1
// baseline (speedup 1.0000x reference)
#include <cuda_runtime.h>
#include <math.h>

// Problem constants
#define B_   2
#define L_   2048
#define D_   1024
#define H_   16
#define G_   2
#define HPG_ 8
#define DH_  128   // DQK == DV

// Scratch (no cudaMalloc allowed): ~72MB of device globals
__device__ float g_q[(size_t)B_ * L_ * H_ * DH_];
__device__ float g_k[(size_t)B_ * L_ * G_ * DH_];
__device__ float g_v[(size_t)B_ * L_ * G_ * DH_];
__device__ float g_ctx[(size_t)B_ * L_ * H_ * DH_];

// ---------------------------------------------------------------------------
// SGEMM with bias: C[M,N] = A[M,K] @ B[K,N] + bias[N]
// BM=128, BN=128, BK=16, 256 threads, 8x8 per-thread tile.
// All M,N multiples of 128 and K multiples of 16 in this problem (no guards).
// ---------------------------------------------------------------------------
__global__ void __launch_bounds__(256) sgemm_bias_kernel(
    const float* __restrict__ A, const float* __restrict__ Bm,
    const float* __restrict__ bias, float* __restrict__ C,
    int M, int N, int K)
{
    __shared__ float As[16][132];   // transposed: As[k][m]
    __shared__ float Bs[16][132];   // Bs[k][n]

    const int tid = threadIdx.x;
    const int bm = blockIdx.y * 128;
    const int bn = blockIdx.x * 128;
    const int tr = tid >> 4;        // 0..15 -> rows tr*8..tr*8+7
    const int tc = tid & 15;        // 0..15 -> cols tc*8..tc*8+7

    float acc[8][8];
#pragma unroll
    for (int i = 0; i < 8; ++i)
#pragma unroll
        for (int j = 0; j < 8; ++j) acc[i][j] = 0.f;

    const int a_row = tid >> 2;          // 0..63  (two passes: +0, +64)
    const int a_col = (tid & 3) << 2;    // 0,4,8,12
    const int b_row = tid >> 5;          // 0..7   (two passes: +0, +8)
    const int b_col = (tid & 31) << 2;   // 0..124

    for (int kt = 0; kt < K; kt += 16) {
#pragma unroll
        for (int rr = 0; rr < 2; ++rr) {
            int r = a_row + rr * 64;
            float4 av = *(const float4*)(A + (size_t)(bm + r) * K + kt + a_col);
            As[a_col + 0][r] = av.x;
            As[a_col + 1][r] = av.y;
            As[a_col + 2][r] = av.z;
            As[a_col + 3][r] = av.w;
        }
#pragma unroll
        for (int rr = 0; rr < 2; ++rr) {
            int r = b_row + rr * 8;
            *(float4*)&Bs[r][b_col] =
                *(const float4*)(Bm + (size_t)(kt + r) * N + bn + b_col);
        }
        __syncthreads();

#pragma unroll
        for (int kk = 0; kk < 16; ++kk) {
            float a[8], b[8];
#pragma unroll
            for (int i = 0; i < 8; ++i) a[i] = As[kk][tr * 8 + i];
#pragma unroll
            for (int j = 0; j < 8; ++j) b[j] = Bs[kk][tc * 8 + j];
#pragma unroll
            for (int i = 0; i < 8; ++i)
#pragma unroll
                for (int j = 0; j < 8; ++j)
                    acc[i][j] = fmaf(a[i], b[j], acc[i][j]);
        }
        __syncthreads();
    }

#pragma unroll
    for (int i = 0; i < 8; ++i) {
        int row = bm + tr * 8 + i;
#pragma unroll
        for (int j = 0; j < 8; j += 4) {
            int col = bn + tc * 8 + j;
            float4 o;
            o.x = acc[i][j + 0] + bias[col + 0];
            o.y = acc[i][j + 1] + bias[col + 1];
            o.z = acc[i][j + 2] + bias[col + 2];
            o.w = acc[i][j + 3] + bias[col + 3];
            *(float4*)(C + (size_t)row * N + col) = o;
        }
    }
}

// ---------------------------------------------------------------------------
// Flash attention (fp32, causal, GQA): one block = 64 query rows of one head.
// BM=BN=64, DH=128, 256 threads as 16x16:
//   score tile: each thread owns rows ty*4..+3, cols tx*4..+3
//   out tile:   each thread owns rows ty*4..+3, cols {tx*4..+3, 64+tx*4..+3}
// Online softmax state per thread row. Row reductions via 16-lane shfl groups.
// ---------------------------------------------------------------------------
#define FBM  64
#define FBN  64
#define PAD  132
#define PPAD 68

__global__ void __launch_bounds__(256) flash_kernel(const float* __restrict__ qes)
{
    extern __shared__ float sm[];
    float* Qs = sm;                    // [64][132]
    float* Ks = Qs + FBM * PAD;        // [64][132]
    float* Vs = Ks + FBN * PAD;        // [64][132]
    float* Ps = Vs + FBN * PAD;        // [64][68]

    const int tid = threadIdx.x;
    const int tx = tid & 15;
    const int ty = tid >> 4;
    const int qt = blockIdx.x;         // query tile 0..31
    const int bh = blockIdx.y;         // b*H + h
    const int b  = bh >> 4;
    const int h  = bh & 15;
    const int g  = h >> 3;             // kv group

    const float scale = qes[0] * 0.08838834764831845f;   // qes / sqrt(128)

    // Load Q tile (coalesced float4)
    {
        const int d  = (tid & 31) << 2;
        const int i0 = tid >> 5;
#pragma unroll
        for (int it = 0; it < 8; ++it) {
            int i = i0 + it * 8;
            int row = qt * FBM + i;
            *(float4*)&Qs[i * PAD + d] =
                *(const float4*)(g_q + ((size_t)(b * L_ + row) * H_ + h) * DH_ + d);
        }
    }

    float m_i[4], l_i[4], acc[4][8];
#pragma unroll
    for (int i = 0; i < 4; ++i) {
        m_i[i] = -1e30f;
        l_i[i] = 0.f;
#pragma unroll
        for (int c = 0; c < 8; ++c) acc[i][c] = 0.f;
    }

    for (int t = 0; t <= qt; ++t) {
        __syncthreads();   // Q visible (t=0); prev Ps/Vs consumers done (t>0)
        {
            const int d  = (tid & 31) << 2;
            const int j0 = tid >> 5;
#pragma unroll
            for (int it = 0; it < 8; ++it) {
                int j = j0 + it * 8;
                size_t base = ((size_t)(b * L_ + t * FBN + j) * G_ + g) * DH_ + d;
                *(float4*)&Ks[j * PAD + d] = *(const float4*)(g_k + base);
                *(float4*)&Vs[j * PAD + d] = *(const float4*)(g_v + base);
            }
        }
        __syncthreads();

        // S = Q @ K^T  (4x4 per thread)
        float s[4][4];
#pragma unroll
        for (int i = 0; i < 4; ++i)
#pragma unroll
            for (int j = 0; j < 4; ++j) s[i][j] = 0.f;

        for (int d = 0; d < DH_; d += 4) {
            float4 qv[4], kv[4];
#pragma unroll
            for (int i = 0; i < 4; ++i)
                qv[i] = *(const float4*)&Qs[(ty * 4 + i) * PAD + d];
#pragma unroll
            for (int j = 0; j < 4; ++j)
                kv[j] = *(const float4*)&Ks[(tx * 4 + j) * PAD + d];
#pragma unroll
            for (int i = 0; i < 4; ++i)
#pragma unroll
                for (int j = 0; j < 4; ++j)
                    s[i][j] += qv[i].x * kv[j].x + qv[i].y * kv[j].y +
                               qv[i].z * kv[j].z + qv[i].w * kv[j].w;
        }

        // scale + causal mask (tile-diagonal only: FBM==FBN, bases aligned)
        const bool diag = (t == qt);
#pragma unroll
        for (int i = 0; i < 4; ++i)
#pragma unroll
            for (int j = 0; j < 4; ++j) {
                float v = s[i][j] * scale;
                if (diag && (tx * 4 + j) > (ty * 4 + i)) v = -1e30f;
                s[i][j] = v;
            }

        // Online softmax update (row reductions across 16-lane tx groups)
#pragma unroll
        for (int i = 0; i < 4; ++i) {
            float r = fmaxf(fmaxf(s[i][0], s[i][1]), fmaxf(s[i][2], s[i][3]));
#pragma unroll
            for (int off = 8; off > 0; off >>= 1)
                r = fmaxf(r, __shfl_xor_sync(0xffffffffu, r, off));
            float mn = fmaxf(m_i[i], r);
            float alpha = __expf(m_i[i] - mn);
            float rs = 0.f;
#pragma unroll
            for (int j = 0; j < 4; ++j) {
                float p = __expf(s[i][j] - mn);
                s[i][j] = p;
                rs += p;
            }
#pragma unroll
            for (int off = 8; off > 0; off >>= 1)
                rs += __shfl_xor_sync(0xffffffffu, rs, off);
            l_i[i] = l_i[i] * alpha + rs;
            m_i[i] = mn;
#pragma unroll
            for (int c = 0; c < 8; ++c) acc[i][c] *= alpha;
#pragma unroll
            for (int j = 0; j < 4; ++j)
                Ps[(ty * 4 + i) * PPAD + tx * 4 + j] = s[i][j];
        }
        __syncthreads();

        // O += P @ V   (cols: tx*4..+3 and 64+tx*4..+3 -> conflict-free LDS.128)
        for (int j = 0; j < FBN; ++j) {
            float4 v0 = *(const float4*)&Vs[j * PAD + tx * 4];
            float4 v1 = *(const float4*)&Vs[j * PAD + 64 + tx * 4];
#pragma unroll
            for (int i = 0; i < 4; ++i) {
                float p = Ps[(ty * 4 + i) * PPAD + j];
                acc[i][0] = fmaf(p, v0.x, acc[i][0]);
                acc[i][1] = fmaf(p, v0.y, acc[i][1]);
                acc[i][2] = fmaf(p, v0.z, acc[i][2]);
                acc[i][3] = fmaf(p, v0.w, acc[i][3]);
                acc[i][4] = fmaf(p, v1.x, acc[i][4]);
                acc[i][5] = fmaf(p, v1.y, acc[i][5]);
                acc[i][6] = fmaf(p, v1.z, acc[i][6]);
                acc[i][7] = fmaf(p, v1.w, acc[i][7]);
            }
        }
    }

    // Write ctx[b, row, h, :] = acc / l
#pragma unroll
    for (int i = 0; i < 4; ++i) {
        int row = qt * FBM + ty * 4 + i;
        float inv = 1.f / l_i[i];
        float* dst = g_ctx + ((size_t)(b * L_ + row) * H_ + h) * DH_;
        float4 o0, o1;
        o0.x = acc[i][0] * inv; o0.y = acc[i][1] * inv;
        o0.z = acc[i][2] * inv; o0.w = acc[i][3] * inv;
        o1.x = acc[i][4] * inv; o1.y = acc[i][5] * inv;
        o1.z = acc[i][6] * inv; o1.w = acc[i][7] * inv;
        *(float4*)(dst + tx * 4)      = o0;
        *(float4*)(dst + 64 + tx * 4) = o1;
    }
}

// ---------------------------------------------------------------------------
// Launcher
// ---------------------------------------------------------------------------
extern "C" void kernel_launch(void* const* d_in, const int* in_sizes, int n_in,
                              void* d_out, int out_size)
{
    const float* in_q = (const float*)d_in[0];
    const float* in_k = (const float*)d_in[1];
    const float* in_v = (const float*)d_in[2];
    const float* Wq   = (const float*)d_in[3];
    const float* bq   = (const float*)d_in[4];
    const float* Wk   = (const float*)d_in[5];
    const float* bk   = (const float*)d_in[6];
    const float* Wv   = (const float*)d_in[7];
    const float* bv   = (const float*)d_in[8];
    const float* Wo   = (const float*)d_in[9];
    const float* bo   = (const float*)d_in[10];
    const float* qes  = (const float*)d_in[11];
    float* out = (float*)d_out;

    float *pq, *pk, *pv, *pctx;
    cudaGetSymbolAddress((void**)&pq,   g_q);
    cudaGetSymbolAddress((void**)&pk,   g_k);
    cudaGetSymbolAddress((void**)&pv,   g_v);
    cudaGetSymbolAddress((void**)&pctx, g_ctx);

    const int M = B_ * L_;   // 4096

    // Projections
    sgemm_bias_kernel<<<dim3((H_ * DH_) / 128, M / 128), 256>>>(
        in_q, Wq, bq, pq, M, H_ * DH_, D_);
    sgemm_bias_kernel<<<dim3((G_ * DH_) / 128, M / 128), 256>>>(
        in_k, Wk, bk, pk, M, G_ * DH_, D_);
    sgemm_bias_kernel<<<dim3((G_ * DH_) / 128, M / 128), 256>>>(
        in_v, Wv, bv, pv, M, G_ * DH_, D_);

    // Flash attention
    const int smem = (3 * FBM * PAD + FBM * PPAD) * (int)sizeof(float);
    cudaFuncSetAttribute(flash_kernel,
                         cudaFuncAttributeMaxDynamicSharedMemorySize, smem);
    flash_kernel<<<dim3(L_ / FBM, B_ * H_), 256, smem>>>(qes);

    // Output projection
    sgemm_bias_kernel<<<dim3(D_ / 128, M / 128), 256>>>(
        pctx, Wo, bo, out, M, D_, H_ * DH_);
}

// round 5
// speedup vs baseline: 4.0427x; 4.0427x over previous
#include <cuda_runtime.h>
#include <math.h>

// Problem constants
#define B_   2
#define L_   2048
#define D_   1024
#define H_   16
#define G_   2
#define DH_  128

// Scratch (no cudaMalloc allowed)
__device__ float g_q[(size_t)B_ * L_ * H_ * DH_];
__device__ float g_k[(size_t)B_ * L_ * G_ * DH_];
__device__ float g_v[(size_t)B_ * L_ * G_ * DH_];
__device__ float g_ctx[(size_t)B_ * L_ * H_ * DH_];

__device__ __forceinline__ unsigned f2tf(float x) {
    unsigned r;
    asm("cvt.rna.tf32.f32 %0, %1;" : "=r"(r) : "f"(x));
    return r;
}

__device__ __forceinline__ void mma_tf32(float c[4],
    unsigned a0, unsigned a1, unsigned a2, unsigned a3,
    unsigned b0, unsigned b1)
{
    asm("mma.sync.aligned.m16n8k8.row.col.f32.tf32.tf32.f32 "
        "{%0,%1,%2,%3},{%4,%5,%6,%7},{%8,%9},{%0,%1,%2,%3};"
        : "+f"(c[0]), "+f"(c[1]), "+f"(c[2]), "+f"(c[3])
        : "r"(a0), "r"(a1), "r"(a2), "r"(a3), "r"(b0), "r"(b1));
}

// ---------------------------------------------------------------------------
// TF32 GEMM with bias: C[M,N] = A[M,K] @ B[K,N] + bias[N]
// BM=128, BN=128, BK=16, 256 threads (8 warps, 4x2), warp tile 32x64.
// ---------------------------------------------------------------------------
#define APITCH 20
#define BPITCH 136

__global__ void __launch_bounds__(256) gemm_tf32_kernel(
    const float* __restrict__ A, const float* __restrict__ Bm,
    const float* __restrict__ bias, float* __restrict__ C,
    int M, int N, int K)
{
    __shared__ unsigned As[128][APITCH];   // [row][k] tf32
    __shared__ unsigned Bs[16][BPITCH];    // [k][col] tf32

    const int tid  = threadIdx.x;
    const int warp = tid >> 5, lane = tid & 31;
    const int wm = warp >> 1, wn = warp & 1;
    const int gid = lane >> 2, tig = lane & 3;
    const int bm = blockIdx.y * 128, bn = blockIdx.x * 128;

    float acc[2][8][4];
#pragma unroll
    for (int mi = 0; mi < 2; ++mi)
#pragma unroll
        for (int ni = 0; ni < 8; ++ni)
#pragma unroll
            for (int r = 0; r < 4; ++r) acc[mi][ni][r] = 0.f;

    const int ar = tid >> 2, ac = (tid & 3) << 2;   // A: 64 rows x 16 (x2)
    const int br = tid >> 5, bc = (tid & 31) << 2;  // B: 8 rows x 128 (x2)

    for (int kt = 0; kt < K; kt += 16) {
#pragma unroll
        for (int rr = 0; rr < 2; ++rr) {
            int r = ar + rr * 64;
            float4 v = *(const float4*)(A + (size_t)(bm + r) * K + kt + ac);
            uint4 u = { f2tf(v.x), f2tf(v.y), f2tf(v.z), f2tf(v.w) };
            *(uint4*)&As[r][ac] = u;
        }
#pragma unroll
        for (int rr = 0; rr < 2; ++rr) {
            int r = br + rr * 8;
            float4 v = *(const float4*)(Bm + (size_t)(kt + r) * N + bn + bc);
            uint4 u = { f2tf(v.x), f2tf(v.y), f2tf(v.z), f2tf(v.w) };
            *(uint4*)&Bs[r][bc] = u;
        }
        __syncthreads();

#pragma unroll
        for (int kk = 0; kk < 2; ++kk) {
            const int k0 = kk * 8;
            unsigned a[2][4];
#pragma unroll
            for (int mi = 0; mi < 2; ++mi) {
                int row = wm * 32 + mi * 16 + gid;
                a[mi][0] = As[row][k0 + tig];
                a[mi][1] = As[row + 8][k0 + tig];
                a[mi][2] = As[row][k0 + tig + 4];
                a[mi][3] = As[row + 8][k0 + tig + 4];
            }
#pragma unroll
            for (int ni = 0; ni < 8; ++ni) {
                int col = wn * 64 + ni * 8 + gid;
                unsigned b0 = Bs[k0 + tig][col];
                unsigned b1 = Bs[k0 + tig + 4][col];
                mma_tf32(acc[0][ni], a[0][0], a[0][1], a[0][2], a[0][3], b0, b1);
                mma_tf32(acc[1][ni], a[1][0], a[1][1], a[1][2], a[1][3], b0, b1);
            }
        }
        __syncthreads();
    }

#pragma unroll
    for (int mi = 0; mi < 2; ++mi)
#pragma unroll
        for (int ni = 0; ni < 8; ++ni) {
            int row = bm + wm * 32 + mi * 16 + gid;
            int col = bn + wn * 64 + ni * 8 + 2 * tig;
            float bx = bias[col], by = bias[col + 1];
            float2 o0 = { acc[mi][ni][0] + bx, acc[mi][ni][1] + by };
            float2 o1 = { acc[mi][ni][2] + bx, acc[mi][ni][3] + by };
            *(float2*)(C + (size_t)row * N + col) = o0;
            *(float2*)(C + (size_t)(row + 8) * N + col) = o1;
        }
}

// ---------------------------------------------------------------------------
// TF32 flash attention (causal, GQA). Block: 128 q rows of one head.
// 8 warps; warp w owns q rows w*16..w*16+15. KV tiles of 64.
// ---------------------------------------------------------------------------
#define QP 132
#define KP 132
#define VP 136
#define PP 68

__global__ void __launch_bounds__(256) flash_tf32_kernel(const float* __restrict__ qes)
{
    extern __shared__ unsigned sm[];
    unsigned (*Qs)[QP] = (unsigned(*)[QP])sm;                        // [128][132]
    unsigned (*Ks)[KP] = (unsigned(*)[KP])(sm + 128 * QP);           // [64][132]
    unsigned (*Vs)[VP] = (unsigned(*)[VP])(sm + 128 * QP + 64 * KP); // [64][136]
    unsigned (*Ps)[PP] = (unsigned(*)[PP])(sm + 128 * QP + 64 * KP + 64 * VP); // [128][68]

    const int tid  = threadIdx.x;
    const int warp = tid >> 5, lane = tid & 31;
    const int gid = lane >> 2, tig = lane & 3;
    const int qt = (int)gridDim.x - 1 - (int)blockIdx.x;   // heavy tiles first
    const int bh = blockIdx.y;
    const int b = bh >> 4, h = bh & 15, g = h >> 3;

    const float scale = qes[0] * 0.08838834764831845f;  // qes / sqrt(128)

    // Load Q tile, pre-scaled, tf32
    {
        const int d = (tid & 31) << 2;
        const int r0 = tid >> 5;
#pragma unroll
        for (int it = 0; it < 16; ++it) {
            int r = r0 + it * 8;
            float4 v = *(const float4*)(g_q +
                ((size_t)(b * L_ + qt * 128 + r) * H_ + h) * DH_ + d);
            uint4 u = { f2tf(v.x * scale), f2tf(v.y * scale),
                        f2tf(v.z * scale), f2tf(v.w * scale) };
            *(uint4*)&Qs[r][d] = u;
        }
    }

    float m0 = -1e30f, m1 = -1e30f, l0 = 0.f, l1 = 0.f;
    float o[16][4];
#pragma unroll
    for (int ni = 0; ni < 16; ++ni)
#pragma unroll
        for (int r = 0; r < 4; ++r) o[ni][r] = 0.f;

    const int prow = warp * 16 + gid;
    const int ntiles = 2 * (qt + 1);

    for (int t = 0; t < ntiles; ++t) {
        __syncthreads();
        // Load K,V tile (tf32)
        {
            const int d = (tid & 31) << 2;
            const int j0 = tid >> 5;
#pragma unroll
            for (int it = 0; it < 8; ++it) {
                int j = j0 + it * 8;
                size_t base = ((size_t)(b * L_ + t * 64 + j) * G_ + g) * DH_ + d;
                float4 kv = *(const float4*)(g_k + base);
                uint4 uk = { f2tf(kv.x), f2tf(kv.y), f2tf(kv.z), f2tf(kv.w) };
                *(uint4*)&Ks[j][d] = uk;
                float4 vv = *(const float4*)(g_v + base);
                uint4 uv = { f2tf(vv.x), f2tf(vv.y), f2tf(vv.z), f2tf(vv.w) };
                *(uint4*)&Vs[j][d] = uv;
            }
        }
        __syncthreads();

        // S = Q @ K^T  (warp rows prow, prow+8; 8 n-tiles of 8)
        float s[8][4];
#pragma unroll
        for (int ni = 0; ni < 8; ++ni)
#pragma unroll
            for (int r = 0; r < 4; ++r) s[ni][r] = 0.f;

#pragma unroll
        for (int kk = 0; kk < 16; ++kk) {
            const int k0 = kk * 8;
            unsigned a0 = Qs[prow][k0 + tig];
            unsigned a1 = Qs[prow + 8][k0 + tig];
            unsigned a2 = Qs[prow][k0 + tig + 4];
            unsigned a3 = Qs[prow + 8][k0 + tig + 4];
#pragma unroll
            for (int ni = 0; ni < 8; ++ni) {
                unsigned b0 = Ks[ni * 8 + gid][k0 + tig];
                unsigned b1 = Ks[ni * 8 + gid][k0 + tig + 4];
                mma_tf32(s[ni], a0, a1, a2, a3, b0, b1);
            }
        }

        // Causal mask (only tiles intersecting the diagonal)
        const int rowg0 = qt * 128 + warp * 16 + gid;
        const int rowg1 = rowg0 + 8;
        if (t >= 2 * qt) {
#pragma unroll
            for (int ni = 0; ni < 8; ++ni) {
                int c0 = t * 64 + ni * 8 + 2 * tig;
                if (c0 > rowg0)     s[ni][0] = -1e30f;
                if (c0 + 1 > rowg0) s[ni][1] = -1e30f;
                if (c0 > rowg1)     s[ni][2] = -1e30f;
                if (c0 + 1 > rowg1) s[ni][3] = -1e30f;
            }
        }

        // Online softmax
        float rmax0 = -1e30f, rmax1 = -1e30f;
#pragma unroll
        for (int ni = 0; ni < 8; ++ni) {
            rmax0 = fmaxf(rmax0, fmaxf(s[ni][0], s[ni][1]));
            rmax1 = fmaxf(rmax1, fmaxf(s[ni][2], s[ni][3]));
        }
        rmax0 = fmaxf(rmax0, __shfl_xor_sync(0xffffffffu, rmax0, 1));
        rmax0 = fmaxf(rmax0, __shfl_xor_sync(0xffffffffu, rmax0, 2));
        rmax1 = fmaxf(rmax1, __shfl_xor_sync(0xffffffffu, rmax1, 1));
        rmax1 = fmaxf(rmax1, __shfl_xor_sync(0xffffffffu, rmax1, 2));

        float mn0 = fmaxf(m0, rmax0), mn1 = fmaxf(m1, rmax1);
        float al0 = __expf(m0 - mn0), al1 = __expf(m1 - mn1);
        float rs0 = 0.f, rs1 = 0.f;
#pragma unroll
        for (int ni = 0; ni < 8; ++ni) {
            s[ni][0] = __expf(s[ni][0] - mn0); rs0 += s[ni][0];
            s[ni][1] = __expf(s[ni][1] - mn0); rs0 += s[ni][1];
            s[ni][2] = __expf(s[ni][2] - mn1); rs1 += s[ni][2];
            s[ni][3] = __expf(s[ni][3] - mn1); rs1 += s[ni][3];
        }
        rs0 += __shfl_xor_sync(0xffffffffu, rs0, 1);
        rs0 += __shfl_xor_sync(0xffffffffu, rs0, 2);
        rs1 += __shfl_xor_sync(0xffffffffu, rs1, 1);
        rs1 += __shfl_xor_sync(0xffffffffu, rs1, 2);
        l0 = l0 * al0 + rs0; m0 = mn0;
        l1 = l1 * al1 + rs1; m1 = mn1;

#pragma unroll
        for (int ni = 0; ni < 16; ++ni) {
            o[ni][0] *= al0; o[ni][1] *= al0;
            o[ni][2] *= al1; o[ni][3] *= al1;
        }

        // P -> smem (warp-private rows, tf32)
#pragma unroll
        for (int ni = 0; ni < 8; ++ni) {
            int pc = ni * 8 + 2 * tig;
            uint2 u0 = { f2tf(s[ni][0]), f2tf(s[ni][1]) };
            uint2 u1 = { f2tf(s[ni][2]), f2tf(s[ni][3]) };
            *(uint2*)&Ps[prow][pc]     = u0;
            *(uint2*)&Ps[prow + 8][pc] = u1;
        }
        __syncwarp();

        // O += P @ V
#pragma unroll
        for (int kk = 0; kk < 8; ++kk) {
            const int k0 = kk * 8;
            unsigned a0 = Ps[prow][k0 + tig];
            unsigned a1 = Ps[prow + 8][k0 + tig];
            unsigned a2 = Ps[prow][k0 + tig + 4];
            unsigned a3 = Ps[prow + 8][k0 + tig + 4];
#pragma unroll
            for (int ni = 0; ni < 16; ++ni) {
                unsigned b0 = Vs[k0 + tig][ni * 8 + gid];
                unsigned b1 = Vs[k0 + tig + 4][ni * 8 + gid];
                mma_tf32(o[ni], a0, a1, a2, a3, b0, b1);
            }
        }
    }

    // Epilogue: O / l -> g_ctx
    const float inv0 = 1.f / l0, inv1 = 1.f / l1;
    const int r0 = qt * 128 + warp * 16 + gid;
    float* dst0 = g_ctx + ((size_t)(b * L_ + r0) * H_ + h) * DH_;
    float* dst1 = g_ctx + ((size_t)(b * L_ + r0 + 8) * H_ + h) * DH_;
#pragma unroll
    for (int ni = 0; ni < 16; ++ni) {
        int col = ni * 8 + 2 * tig;
        float2 v0 = { o[ni][0] * inv0, o[ni][1] * inv0 };
        float2 v1 = { o[ni][2] * inv1, o[ni][3] * inv1 };
        *(float2*)(dst0 + col) = v0;
        *(float2*)(dst1 + col) = v1;
    }
}

// ---------------------------------------------------------------------------
// Launcher
// ---------------------------------------------------------------------------
extern "C" void kernel_launch(void* const* d_in, const int* in_sizes, int n_in,
                              void* d_out, int out_size)
{
    const float* in_q = (const float*)d_in[0];
    const float* in_k = (const float*)d_in[1];
    const float* in_v = (const float*)d_in[2];
    const float* Wq   = (const float*)d_in[3];
    const float* bq   = (const float*)d_in[4];
    const float* Wk   = (const float*)d_in[5];
    const float* bk   = (const float*)d_in[6];
    const float* Wv   = (const float*)d_in[7];
    const float* bv   = (const float*)d_in[8];
    const float* Wo   = (const float*)d_in[9];
    const float* bo   = (const float*)d_in[10];
    const float* qes  = (const float*)d_in[11];
    float* out = (float*)d_out;

    float *pq, *pk, *pv, *pctx;
    cudaGetSymbolAddress((void**)&pq,   g_q);
    cudaGetSymbolAddress((void**)&pk,   g_k);
    cudaGetSymbolAddress((void**)&pv,   g_v);
    cudaGetSymbolAddress((void**)&pctx, g_ctx);

    const int M = B_ * L_;   // 4096

    gemm_tf32_kernel<<<dim3((H_ * DH_) / 128, M / 128), 256>>>(
        in_q, Wq, bq, pq, M, H_ * DH_, D_);
    gemm_tf32_kernel<<<dim3((G_ * DH_) / 128, M / 128), 256>>>(
        in_k, Wk, bk, pk, M, G_ * DH_, D_);
    gemm_tf32_kernel<<<dim3((G_ * DH_) / 128, M / 128), 256>>>(
        in_v, Wv, bv, pv, M, G_ * DH_, D_);

    const int smem = (128 * QP + 64 * KP + 64 * VP + 128 * PP) * (int)sizeof(unsigned);
    cudaFuncSetAttribute(flash_tf32_kernel,
                         cudaFuncAttributeMaxDynamicSharedMemorySize, smem);
    flash_tf32_kernel<<<dim3(L_ / 128, B_ * H_), 256, smem>>>(qes);

    gemm_tf32_kernel<<<dim3(D_ / 128, M / 128), 256>>>(
        pctx, Wo, bo, out, M, D_, H_ * DH_);
}

// round 6
// speedup vs baseline: 4.1762x; 1.0330x over previous
#include <cuda_runtime.h>
#include <math.h>

// Problem constants
#define B_   2
#define L_   2048
#define D_   1024
#define H_   16
#define G_   2
#define DH_  128

// Scratch (no cudaMalloc allowed)
__device__ float g_q[(size_t)B_ * L_ * H_ * DH_];
__device__ float g_k[(size_t)B_ * L_ * G_ * DH_];
__device__ float g_v[(size_t)B_ * L_ * G_ * DH_];
__device__ float g_ctx[(size_t)B_ * L_ * H_ * DH_];

__device__ __forceinline__ unsigned f2tf(float x) {
    unsigned r;
    asm("cvt.rna.tf32.f32 %0, %1;" : "=r"(r) : "f"(x));
    return r;
}

__device__ __forceinline__ void mma_tf32(float c[4],
    unsigned a0, unsigned a1, unsigned a2, unsigned a3,
    unsigned b0, unsigned b1)
{
    asm("mma.sync.aligned.m16n8k8.row.col.f32.tf32.tf32.f32 "
        "{%0,%1,%2,%3},{%4,%5,%6,%7},{%8,%9},{%0,%1,%2,%3};"
        : "+f"(c[0]), "+f"(c[1]), "+f"(c[2]), "+f"(c[3])
        : "r"(a0), "r"(a1), "r"(a2), "r"(a3), "r"(b0), "r"(b1));
}

// ---------------------------------------------------------------------------
// TF32 GEMM with bias, double-buffered: C[M,N] = A[M,K] @ B[K,N] + bias[N]
// BM=128, BN=128, BK=16, 256 threads (8 warps, 4x2), warp tile 32x64.
// ---------------------------------------------------------------------------
#define APITCH 20
#define BPITCH 136

__global__ void __launch_bounds__(256) gemm_tf32_kernel(
    const float* __restrict__ A, const float* __restrict__ Bm,
    const float* __restrict__ bias, float* __restrict__ C,
    int M, int N, int K)
{
    __shared__ unsigned As[2][128][APITCH];
    __shared__ unsigned Bs[2][16][BPITCH];

    const int tid  = threadIdx.x;
    const int warp = tid >> 5, lane = tid & 31;
    const int wm = warp >> 1, wn = warp & 1;
    const int gid = lane >> 2, tig = lane & 3;
    const int bm = blockIdx.y * 128, bn = blockIdx.x * 128;

    float acc[2][8][4];
#pragma unroll
    for (int mi = 0; mi < 2; ++mi)
#pragma unroll
        for (int ni = 0; ni < 8; ++ni)
#pragma unroll
            for (int r = 0; r < 4; ++r) acc[mi][ni][r] = 0.f;

    const int ar = tid >> 2, ac = (tid & 3) << 2;
    const int br = tid >> 5, bc = (tid & 31) << 2;

    float4 ra[2], rb[2];
    // Prologue: load kt=0
#pragma unroll
    for (int rr = 0; rr < 2; ++rr)
        ra[rr] = *(const float4*)(A + (size_t)(bm + ar + rr * 64) * K + ac);
#pragma unroll
    for (int rr = 0; rr < 2; ++rr)
        rb[rr] = *(const float4*)(Bm + (size_t)(br + rr * 8) * N + bn + bc);
    // Store to buf 0
#pragma unroll
    for (int rr = 0; rr < 2; ++rr) {
        int r = ar + rr * 64;
        As[0][r][ac + 0] = f2tf(ra[rr].x);
        As[0][r][ac + 1] = f2tf(ra[rr].y);
        As[0][r][ac + 2] = f2tf(ra[rr].z);
        As[0][r][ac + 3] = f2tf(ra[rr].w);
        uint4 u = { f2tf(rb[rr].x), f2tf(rb[rr].y), f2tf(rb[rr].z), f2tf(rb[rr].w) };
        *(uint4*)&Bs[0][br + rr * 8][bc] = u;
    }

    int buf = 0;
    for (int kt = 0; kt < K; kt += 16) {
        __syncthreads();
        const bool more = (kt + 16) < K;
        if (more) {
#pragma unroll
            for (int rr = 0; rr < 2; ++rr)
                ra[rr] = *(const float4*)(A + (size_t)(bm + ar + rr * 64) * K + kt + 16 + ac);
#pragma unroll
            for (int rr = 0; rr < 2; ++rr)
                rb[rr] = *(const float4*)(Bm + (size_t)(kt + 16 + br + rr * 8) * N + bn + bc);
        }

#pragma unroll
        for (int kk = 0; kk < 2; ++kk) {
            const int k0 = kk * 8;
            unsigned a[2][4];
#pragma unroll
            for (int mi = 0; mi < 2; ++mi) {
                int row = wm * 32 + mi * 16 + gid;
                a[mi][0] = As[buf][row][k0 + tig];
                a[mi][1] = As[buf][row + 8][k0 + tig];
                a[mi][2] = As[buf][row][k0 + tig + 4];
                a[mi][3] = As[buf][row + 8][k0 + tig + 4];
            }
#pragma unroll
            for (int ni = 0; ni < 8; ++ni) {
                int col = wn * 64 + ni * 8 + gid;
                unsigned b0 = Bs[buf][k0 + tig][col];
                unsigned b1 = Bs[buf][k0 + tig + 4][col];
                mma_tf32(acc[0][ni], a[0][0], a[0][1], a[0][2], a[0][3], b0, b1);
                mma_tf32(acc[1][ni], a[1][0], a[1][1], a[1][2], a[1][3], b0, b1);
            }
        }

        if (more) {
            int nb = buf ^ 1;
#pragma unroll
            for (int rr = 0; rr < 2; ++rr) {
                int r = ar + rr * 64;
                As[nb][r][ac + 0] = f2tf(ra[rr].x);
                As[nb][r][ac + 1] = f2tf(ra[rr].y);
                As[nb][r][ac + 2] = f2tf(ra[rr].z);
                As[nb][r][ac + 3] = f2tf(ra[rr].w);
                uint4 u = { f2tf(rb[rr].x), f2tf(rb[rr].y), f2tf(rb[rr].z), f2tf(rb[rr].w) };
                *(uint4*)&Bs[nb][br + rr * 8][bc] = u;
            }
        }
        buf ^= 1;
    }

#pragma unroll
    for (int mi = 0; mi < 2; ++mi)
#pragma unroll
        for (int ni = 0; ni < 8; ++ni) {
            int row = bm + wm * 32 + mi * 16 + gid;
            int col = bn + wn * 64 + ni * 8 + 2 * tig;
            float bx = bias[col], by = bias[col + 1];
            float2 o0 = { acc[mi][ni][0] + bx, acc[mi][ni][1] + by };
            float2 o1 = { acc[mi][ni][2] + bx, acc[mi][ni][3] + by };
            *(float2*)(C + (size_t)row * N + col) = o0;
            *(float2*)(C + (size_t)(row + 8) * N + col) = o1;
        }
}

// ---------------------------------------------------------------------------
// TF32 flash attention (causal, GQA). Block: 128 q rows of one head.
// 8 warps; warp w owns q rows w*16..w*16+15. KV tiles of 64.
// Q lives in smem in MMA-fragment layout (LDS.128 per kk).
// K/V double-buffered through registers (LDG t+1 issued before compute t).
// ---------------------------------------------------------------------------
#define KP 132
#define VP 136
#define PP 68
// Qf: [warp][kk][lane][4regs] = 8*16*32*4 words = 64KB

__global__ void __launch_bounds__(256) flash_tf32_kernel(const float* __restrict__ qes)
{
    extern __shared__ unsigned sm[];
    unsigned* Qf = sm;                                            // 16384 words
    unsigned (*Ks)[KP] = (unsigned(*)[KP])(sm + 16384);           // [64][132]
    unsigned (*Vs)[VP] = (unsigned(*)[VP])(sm + 16384 + 64 * KP); // [64][136]
    unsigned (*Ps)[PP] = (unsigned(*)[PP])(sm + 16384 + 64 * KP + 64 * VP); // [128][68]

    const int tid  = threadIdx.x;
    const int warp = tid >> 5, lane = tid & 31;
    const int gid = lane >> 2, tig = lane & 3;
    const int qt = (int)gridDim.x - 1 - (int)blockIdx.x;   // heavy tiles first
    const int bh = blockIdx.y;
    const int b = bh >> 4, h = bh & 15, g = h >> 3;

    const float scale = qes[0] * 0.08838834764831845f;  // qes / sqrt(128)

    // Load Q tile, pre-scaled, tf32, store in fragment layout
    {
        const int d0 = (tid & 31) << 2;
        const int r0 = tid >> 5;
        const int kk = d0 >> 3;
        const int sub = ((d0 & 7) >= 4) ? 2 : 0;
#pragma unroll
        for (int it = 0; it < 16; ++it) {
            int r = r0 + it * 8;
            float4 v = *(const float4*)(g_q +
                ((size_t)(b * L_ + qt * 128 + r) * H_ + h) * DH_ + d0);
            unsigned u[4] = { f2tf(v.x * scale), f2tf(v.y * scale),
                              f2tf(v.z * scale), f2tf(v.w * scale) };
            int w = r >> 4, rr = r & 15;
            int og = rr & 7, hi = rr >> 3;
            int reg = hi + sub;
            unsigned* base = Qf + (((w * 16 + kk) << 7) | reg);
#pragma unroll
            for (int c = 0; c < 4; ++c)
                base[((og << 2) | c) << 2] = u[c];
        }
    }

    float m0 = -1e30f, m1 = -1e30f, l0 = 0.f, l1 = 0.f;
    float o[16][4];
#pragma unroll
    for (int ni = 0; ni < 16; ++ni)
#pragma unroll
        for (int r = 0; r < 4; ++r) o[ni][r] = 0.f;

    const int prow = warp * 16 + gid;
    const int ntiles = 2 * (qt + 1);

    const int d0 = (tid & 31) << 2;
    const int j0 = tid >> 5;

    float4 pk[8], pv[8];
    // Prologue: load KV tile 0 into registers
#pragma unroll
    for (int it = 0; it < 8; ++it) {
        int j = j0 + it * 8;
        size_t base = ((size_t)(b * L_ + j) * G_ + g) * DH_ + d0;
        pk[it] = *(const float4*)(g_k + base);
        pv[it] = *(const float4*)(g_v + base);
    }

    for (int t = 0; t < ntiles; ++t) {
        __syncthreads();   // Qf/prev-tile consumers done
        // Commit registers -> smem (tf32)
#pragma unroll
        for (int it = 0; it < 8; ++it) {
            int j = j0 + it * 8;
            uint4 uk = { f2tf(pk[it].x), f2tf(pk[it].y), f2tf(pk[it].z), f2tf(pk[it].w) };
            *(uint4*)&Ks[j][d0] = uk;
            uint4 uv = { f2tf(pv[it].x), f2tf(pv[it].y), f2tf(pv[it].z), f2tf(pv[it].w) };
            *(uint4*)&Vs[j][d0] = uv;
        }
        __syncthreads();

        // Prefetch next KV tile (latency hidden under compute below)
        if (t + 1 < ntiles) {
#pragma unroll
            for (int it = 0; it < 8; ++it) {
                int j = j0 + it * 8;
                size_t base = ((size_t)(b * L_ + (t + 1) * 64 + j) * G_ + g) * DH_ + d0;
                pk[it] = *(const float4*)(g_k + base);
                pv[it] = *(const float4*)(g_v + base);
            }
        }

        // S = Q @ K^T
        float s[8][4];
#pragma unroll
        for (int ni = 0; ni < 8; ++ni)
#pragma unroll
            for (int r = 0; r < 4; ++r) s[ni][r] = 0.f;

#pragma unroll
        for (int kk = 0; kk < 16; ++kk) {
            uint4 af = *(const uint4*)&Qf[(((warp * 16 + kk) << 7) | (lane << 2))];
            const int k0 = kk * 8;
#pragma unroll
            for (int ni = 0; ni < 8; ++ni) {
                unsigned b0 = Ks[ni * 8 + gid][k0 + tig];
                unsigned b1 = Ks[ni * 8 + gid][k0 + tig + 4];
                mma_tf32(s[ni], af.x, af.y, af.z, af.w, b0, b1);
            }
        }

        // Causal mask (only tiles intersecting the diagonal)
        const int rowg0 = qt * 128 + warp * 16 + gid;
        const int rowg1 = rowg0 + 8;
        if (t >= 2 * qt) {
#pragma unroll
            for (int ni = 0; ni < 8; ++ni) {
                int c0 = t * 64 + ni * 8 + 2 * tig;
                if (c0 > rowg0)     s[ni][0] = -1e30f;
                if (c0 + 1 > rowg0) s[ni][1] = -1e30f;
                if (c0 > rowg1)     s[ni][2] = -1e30f;
                if (c0 + 1 > rowg1) s[ni][3] = -1e30f;
            }
        }

        // Online softmax
        float rmax0 = -1e30f, rmax1 = -1e30f;
#pragma unroll
        for (int ni = 0; ni < 8; ++ni) {
            rmax0 = fmaxf(rmax0, fmaxf(s[ni][0], s[ni][1]));
            rmax1 = fmaxf(rmax1, fmaxf(s[ni][2], s[ni][3]));
        }
        rmax0 = fmaxf(rmax0, __shfl_xor_sync(0xffffffffu, rmax0, 1));
        rmax0 = fmaxf(rmax0, __shfl_xor_sync(0xffffffffu, rmax0, 2));
        rmax1 = fmaxf(rmax1, __shfl_xor_sync(0xffffffffu, rmax1, 1));
        rmax1 = fmaxf(rmax1, __shfl_xor_sync(0xffffffffu, rmax1, 2));

        float mn0 = fmaxf(m0, rmax0), mn1 = fmaxf(m1, rmax1);
        float al0 = __expf(m0 - mn0), al1 = __expf(m1 - mn1);
        float rs0 = 0.f, rs1 = 0.f;
#pragma unroll
        for (int ni = 0; ni < 8; ++ni) {
            s[ni][0] = __expf(s[ni][0] - mn0); rs0 += s[ni][0];
            s[ni][1] = __expf(s[ni][1] - mn0); rs0 += s[ni][1];
            s[ni][2] = __expf(s[ni][2] - mn1); rs1 += s[ni][2];
            s[ni][3] = __expf(s[ni][3] - mn1); rs1 += s[ni][3];
        }
        rs0 += __shfl_xor_sync(0xffffffffu, rs0, 1);
        rs0 += __shfl_xor_sync(0xffffffffu, rs0, 2);
        rs1 += __shfl_xor_sync(0xffffffffu, rs1, 1);
        rs1 += __shfl_xor_sync(0xffffffffu, rs1, 2);
        l0 = l0 * al0 + rs0; m0 = mn0;
        l1 = l1 * al1 + rs1; m1 = mn1;

#pragma unroll
        for (int ni = 0; ni < 16; ++ni) {
            o[ni][0] *= al0; o[ni][1] *= al0;
            o[ni][2] *= al1; o[ni][3] *= al1;
        }

        // P -> smem (warp-private rows, tf32)
#pragma unroll
        for (int ni = 0; ni < 8; ++ni) {
            int pc = ni * 8 + 2 * tig;
            uint2 u0 = { f2tf(s[ni][0]), f2tf(s[ni][1]) };
            uint2 u1 = { f2tf(s[ni][2]), f2tf(s[ni][3]) };
            *(uint2*)&Ps[prow][pc]     = u0;
            *(uint2*)&Ps[prow + 8][pc] = u1;
        }
        __syncwarp();

        // O += P @ V
#pragma unroll
        for (int kk = 0; kk < 8; ++kk) {
            const int k0 = kk * 8;
            unsigned a0 = Ps[prow][k0 + tig];
            unsigned a1 = Ps[prow + 8][k0 + tig];
            unsigned a2 = Ps[prow][k0 + tig + 4];
            unsigned a3 = Ps[prow + 8][k0 + tig + 4];
#pragma unroll
            for (int ni = 0; ni < 16; ++ni) {
                unsigned b0 = Vs[k0 + tig][ni * 8 + gid];
                unsigned b1 = Vs[k0 + tig + 4][ni * 8 + gid];
                mma_tf32(o[ni], a0, a1, a2, a3, b0, b1);
            }
        }
    }

    // Epilogue: O / l -> g_ctx
    const float inv0 = 1.f / l0, inv1 = 1.f / l1;
    const int r0 = qt * 128 + warp * 16 + gid;
    float* dst0 = g_ctx + ((size_t)(b * L_ + r0) * H_ + h) * DH_;
    float* dst1 = g_ctx + ((size_t)(b * L_ + r0 + 8) * H_ + h) * DH_;
#pragma unroll
    for (int ni = 0; ni < 16; ++ni) {
        int col = ni * 8 + 2 * tig;
        float2 v0 = { o[ni][0] * inv0, o[ni][1] * inv0 };
        float2 v1 = { o[ni][2] * inv1, o[ni][3] * inv1 };
        *(float2*)(dst0 + col) = v0;
        *(float2*)(dst1 + col) = v1;
    }
}

// ---------------------------------------------------------------------------
// Launcher
// ---------------------------------------------------------------------------
extern "C" void kernel_launch(void* const* d_in, const int* in_sizes, int n_in,
                              void* d_out, int out_size)
{
    const float* in_q = (const float*)d_in[0];
    const float* in_k = (const float*)d_in[1];
    const float* in_v = (const float*)d_in[2];
    const float* Wq   = (const float*)d_in[3];
    const float* bq   = (const float*)d_in[4];
    const float* Wk   = (const float*)d_in[5];
    const float* bk   = (const float*)d_in[6];
    const float* Wv   = (const float*)d_in[7];
    const float* bv   = (const float*)d_in[8];
    const float* Wo   = (const float*)d_in[9];
    const float* bo   = (const float*)d_in[10];
    const float* qes  = (const float*)d_in[11];
    float* out = (float*)d_out;

    float *pq, *pk, *pv, *pctx;
    cudaGetSymbolAddress((void**)&pq,   g_q);
    cudaGetSymbolAddress((void**)&pk,   g_k);
    cudaGetSymbolAddress((void**)&pv,   g_v);
    cudaGetSymbolAddress((void**)&pctx, g_ctx);

    const int M = B_ * L_;   // 4096

    gemm_tf32_kernel<<<dim3((H_ * DH_) / 128, M / 128), 256>>>(
        in_q, Wq, bq, pq, M, H_ * DH_, D_);
    gemm_tf32_kernel<<<dim3((G_ * DH_) / 128, M / 128), 256>>>(
        in_k, Wk, bk, pk, M, G_ * DH_, D_);
    gemm_tf32_kernel<<<dim3((G_ * DH_) / 128, M / 128), 256>>>(
        in_v, Wv, bv, pv, M, G_ * DH_, D_);

    const int smem = (16384 + 64 * KP + 64 * VP + 128 * PP) * (int)sizeof(unsigned);
    cudaFuncSetAttribute(flash_tf32_kernel,
                         cudaFuncAttributeMaxDynamicSharedMemorySize, smem);
    flash_tf32_kernel<<<dim3(L_ / 128, B_ * H_), 256, smem>>>(qes);

    gemm_tf32_kernel<<<dim3(D_ / 128, M / 128), 256>>>(
        pctx, Wo, bo, out, M, D_, H_ * DH_);
}

// round 7
// speedup vs baseline: 4.5044x; 1.0786x over previous
#include <cuda_runtime.h>
#include <math.h>

// Problem constants
#define B_   2
#define L_   2048
#define D_   1024
#define H_   16
#define G_   2
#define DH_  128

// Scratch (no cudaMalloc allowed)
__device__ float g_q[(size_t)B_ * L_ * H_ * DH_];
__device__ float g_k[(size_t)B_ * L_ * G_ * DH_];
__device__ float g_v[(size_t)B_ * L_ * G_ * DH_];
__device__ float g_ctx[(size_t)B_ * L_ * H_ * DH_];

__device__ __forceinline__ unsigned f2tf(float x) {
    unsigned r;
    asm("cvt.rna.tf32.f32 %0, %1;" : "=r"(r) : "f"(x));
    return r;
}

__device__ __forceinline__ void mma_tf32(float c[4],
    unsigned a0, unsigned a1, unsigned a2, unsigned a3,
    unsigned b0, unsigned b1)
{
    asm("mma.sync.aligned.m16n8k8.row.col.f32.tf32.tf32.f32 "
        "{%0,%1,%2,%3},{%4,%5,%6,%7},{%8,%9},{%0,%1,%2,%3};"
        : "+f"(c[0]), "+f"(c[1]), "+f"(c[2]), "+f"(c[3])
        : "r"(a0), "r"(a1), "r"(a2), "r"(a3), "r"(b0), "r"(b1));
}

// ---------------------------------------------------------------------------
// TF32 GEMM body with bias, double-buffered: C = A[.,K] @ B[K,N] + bias[N]
// BM=128, BN=128, BK=16, 256 threads (8 warps, 4x2), warp tile 32x64.
// ---------------------------------------------------------------------------
#define APITCH 20
#define BPITCH 136

__device__ __forceinline__ void gemm_body(
    const float* __restrict__ A, const float* __restrict__ Bm,
    const float* __restrict__ bias, float* __restrict__ C,
    int N, int K, int bm, int bn)
{
    __shared__ unsigned As[2][128][APITCH];
    __shared__ unsigned Bs[2][16][BPITCH];

    const int tid  = threadIdx.x;
    const int warp = tid >> 5, lane = tid & 31;
    const int wm = warp >> 1, wn = warp & 1;
    const int gid = lane >> 2, tig = lane & 3;

    float acc[2][8][4];
#pragma unroll
    for (int mi = 0; mi < 2; ++mi)
#pragma unroll
        for (int ni = 0; ni < 8; ++ni)
#pragma unroll
            for (int r = 0; r < 4; ++r) acc[mi][ni][r] = 0.f;

    const int ar = tid >> 2, ac = (tid & 3) << 2;
    const int br = tid >> 5, bc = (tid & 31) << 2;

    float4 ra[2], rb[2];
#pragma unroll
    for (int rr = 0; rr < 2; ++rr)
        ra[rr] = *(const float4*)(A + (size_t)(bm + ar + rr * 64) * K + ac);
#pragma unroll
    for (int rr = 0; rr < 2; ++rr)
        rb[rr] = *(const float4*)(Bm + (size_t)(br + rr * 8) * N + bn + bc);
#pragma unroll
    for (int rr = 0; rr < 2; ++rr) {
        int r = ar + rr * 64;
        As[0][r][ac + 0] = f2tf(ra[rr].x);
        As[0][r][ac + 1] = f2tf(ra[rr].y);
        As[0][r][ac + 2] = f2tf(ra[rr].z);
        As[0][r][ac + 3] = f2tf(ra[rr].w);
        uint4 u = { f2tf(rb[rr].x), f2tf(rb[rr].y), f2tf(rb[rr].z), f2tf(rb[rr].w) };
        *(uint4*)&Bs[0][br + rr * 8][bc] = u;
    }

    int buf = 0;
    for (int kt = 0; kt < K; kt += 16) {
        __syncthreads();
        const bool more = (kt + 16) < K;
        if (more) {
#pragma unroll
            for (int rr = 0; rr < 2; ++rr)
                ra[rr] = *(const float4*)(A + (size_t)(bm + ar + rr * 64) * K + kt + 16 + ac);
#pragma unroll
            for (int rr = 0; rr < 2; ++rr)
                rb[rr] = *(const float4*)(Bm + (size_t)(kt + 16 + br + rr * 8) * N + bn + bc);
        }

#pragma unroll
        for (int kk = 0; kk < 2; ++kk) {
            const int k0 = kk * 8;
            unsigned a[2][4];
#pragma unroll
            for (int mi = 0; mi < 2; ++mi) {
                int row = wm * 32 + mi * 16 + gid;
                a[mi][0] = As[buf][row][k0 + tig];
                a[mi][1] = As[buf][row + 8][k0 + tig];
                a[mi][2] = As[buf][row][k0 + tig + 4];
                a[mi][3] = As[buf][row + 8][k0 + tig + 4];
            }
#pragma unroll
            for (int ni = 0; ni < 8; ++ni) {
                int col = wn * 64 + ni * 8 + gid;
                unsigned b0 = Bs[buf][k0 + tig][col];
                unsigned b1 = Bs[buf][k0 + tig + 4][col];
                mma_tf32(acc[0][ni], a[0][0], a[0][1], a[0][2], a[0][3], b0, b1);
                mma_tf32(acc[1][ni], a[1][0], a[1][1], a[1][2], a[1][3], b0, b1);
            }
        }

        if (more) {
            int nb = buf ^ 1;
#pragma unroll
            for (int rr = 0; rr < 2; ++rr) {
                int r = ar + rr * 64;
                As[nb][r][ac + 0] = f2tf(ra[rr].x);
                As[nb][r][ac + 1] = f2tf(ra[rr].y);
                As[nb][r][ac + 2] = f2tf(ra[rr].z);
                As[nb][r][ac + 3] = f2tf(ra[rr].w);
                uint4 u = { f2tf(rb[rr].x), f2tf(rb[rr].y), f2tf(rb[rr].z), f2tf(rb[rr].w) };
                *(uint4*)&Bs[nb][br + rr * 8][bc] = u;
            }
        }
        buf ^= 1;
    }

#pragma unroll
    for (int mi = 0; mi < 2; ++mi)
#pragma unroll
        for (int ni = 0; ni < 8; ++ni) {
            int row = bm + wm * 32 + mi * 16 + gid;
            int col = bn + wn * 64 + ni * 8 + 2 * tig;
            float bx = bias[col], by = bias[col + 1];
            float2 o0 = { acc[mi][ni][0] + bx, acc[mi][ni][1] + by };
            float2 o1 = { acc[mi][ni][2] + bx, acc[mi][ni][3] + by };
            *(float2*)(C + (size_t)row * N + col) = o0;
            *(float2*)(C + (size_t)(row + 8) * N + col) = o1;
        }
}

// Fused Q/K/V projection: grid.x = 512 + 64 + 64 = 640
__global__ void __launch_bounds__(256, 2) gemm3_kernel(
    const float* __restrict__ in_q, const float* __restrict__ Wq,
    const float* __restrict__ bq, float* __restrict__ pq,
    const float* __restrict__ in_k, const float* __restrict__ Wk,
    const float* __restrict__ bk, float* __restrict__ pk,
    const float* __restrict__ in_v, const float* __restrict__ Wv,
    const float* __restrict__ bv, float* __restrict__ pv)
{
    const int blk = blockIdx.x;
    if (blk < 512) {
        gemm_body(in_q, Wq, bq, pq, 2048, 1024, (blk >> 4) * 128, (blk & 15) * 128);
    } else if (blk < 576) {
        int t = blk - 512;
        gemm_body(in_k, Wk, bk, pk, 256, 1024, (t >> 1) * 128, (t & 1) * 128);
    } else {
        int t = blk - 576;
        gemm_body(in_v, Wv, bv, pv, 256, 1024, (t >> 1) * 128, (t & 1) * 128);
    }
}

__global__ void __launch_bounds__(256, 2) gemm_tf32_kernel(
    const float* __restrict__ A, const float* __restrict__ Bm,
    const float* __restrict__ bias, float* __restrict__ C,
    int M, int N, int K)
{
    gemm_body(A, Bm, bias, C, N, K, blockIdx.y * 128, blockIdx.x * 128);
}

// ---------------------------------------------------------------------------
// TF32 flash attention (causal, GQA). Block: 128 q rows of one head.
// 512 threads = 16 warps. Warp (strip s = warp&7, half h = warp>>3):
//   computes S for rows s*16..+15 x kv cols h*32..+31, accumulates partial O
//   over its kv half. Cross-warp softmax (max/sum) via smem exchange.
//   Partial O pairs combined at the end through reused K/V smem.
// ---------------------------------------------------------------------------
#define KP 132
#define VP 136
#define PP 68

__global__ void __launch_bounds__(512) flash_tf32_kernel(const float* __restrict__ qes)
{
    extern __shared__ unsigned sm[];
    unsigned* Qf = sm;                                            // 16384 words
    unsigned (*Ks)[KP] = (unsigned(*)[KP])(sm + 16384);           // [64][132]
    unsigned (*Vs)[VP] = (unsigned(*)[VP])(sm + 16384 + 64 * KP); // [64][136]
    unsigned (*Ps)[PP] = (unsigned(*)[PP])(sm + 16384 + 64 * KP + 64 * VP); // [128][68]
    float* redM = (float*)(sm + 16384 + 64 * KP + 64 * VP + 128 * PP);  // [2][128]
    float* redS = redM + 256;                                            // [2][128]

    const int tid  = threadIdx.x;
    const int warp = tid >> 5, lane = tid & 31;
    const int ws = warp & 7, hf = warp >> 3;
    const int gid = lane >> 2, tig = lane & 3;
    const int qt = (int)gridDim.x - 1 - (int)blockIdx.x;   // heavy tiles first
    const int bh = blockIdx.y;
    const int b = bh >> 4, h = bh & 15, g = h >> 3;

    const float scale = qes[0] * 0.08838834764831845f;  // qes / sqrt(128)

    // Load Q tile, pre-scaled, tf32, store in fragment layout
    {
        const int d0 = (tid & 31) << 2;
        const int r0 = tid >> 5;
        const int kk = d0 >> 3;
        const int sub = ((d0 & 7) >= 4) ? 2 : 0;
#pragma unroll
        for (int it = 0; it < 8; ++it) {
            int r = r0 + it * 16;
            float4 v = *(const float4*)(g_q +
                ((size_t)(b * L_ + qt * 128 + r) * H_ + h) * DH_ + d0);
            unsigned u[4] = { f2tf(v.x * scale), f2tf(v.y * scale),
                              f2tf(v.z * scale), f2tf(v.w * scale) };
            int w = r >> 4, rr = r & 15;
            int og = rr & 7, hi = rr >> 3;
            int reg = hi + sub;
            unsigned* base = Qf + (((w * 16 + kk) << 7) | reg);
#pragma unroll
            for (int c = 0; c < 4; ++c)
                base[((og << 2) | c) << 2] = u[c];
        }
    }

    float m0 = -1e30f, m1 = -1e30f, l0 = 0.f, l1 = 0.f;
    float o[16][4];
#pragma unroll
    for (int ni = 0; ni < 16; ++ni)
#pragma unroll
        for (int r = 0; r < 4; ++r) o[ni][r] = 0.f;

    const int prow = ws * 16 + gid;
    const int ntiles = 2 * (qt + 1);

    const int d0 = (tid & 31) << 2;
    const int j0 = tid >> 5;

    for (int t = 0; t < ntiles; ++t) {
        __syncthreads();   // prev-tile K/V consumers done
        // Load K,V tile gmem -> smem (tf32)
#pragma unroll
        for (int it = 0; it < 4; ++it) {
            int j = j0 + it * 16;
            size_t base = ((size_t)(b * L_ + t * 64 + j) * G_ + g) * DH_ + d0;
            float4 kv = *(const float4*)(g_k + base);
            uint4 uk = { f2tf(kv.x), f2tf(kv.y), f2tf(kv.z), f2tf(kv.w) };
            *(uint4*)&Ks[j][d0] = uk;
            float4 vv = *(const float4*)(g_v + base);
            uint4 uv = { f2tf(vv.x), f2tf(vv.y), f2tf(vv.z), f2tf(vv.w) };
            *(uint4*)&Vs[j][d0] = uv;
        }
        __syncthreads();

        // S = Q @ K^T  (this warp: rows strip ws, kv cols hf*32..+31)
        float s[4][4];
#pragma unroll
        for (int ni = 0; ni < 4; ++ni)
#pragma unroll
            for (int r = 0; r < 4; ++r) s[ni][r] = 0.f;

#pragma unroll
        for (int kk = 0; kk < 16; ++kk) {
            uint4 af = *(const uint4*)&Qf[(((ws * 16 + kk) << 7) | (lane << 2))];
            const int k0 = kk * 8;
#pragma unroll
            for (int ni = 0; ni < 4; ++ni) {
                int row = hf * 32 + ni * 8 + gid;
                unsigned b0 = Ks[row][k0 + tig];
                unsigned b1 = Ks[row][k0 + tig + 4];
                mma_tf32(s[ni], af.x, af.y, af.z, af.w, b0, b1);
            }
        }

        // Causal mask (only tiles intersecting the diagonal)
        const int rowg0 = qt * 128 + ws * 16 + gid;
        const int rowg1 = rowg0 + 8;
        if (t >= 2 * qt) {
#pragma unroll
            for (int ni = 0; ni < 4; ++ni) {
                int c0 = t * 64 + hf * 32 + ni * 8 + 2 * tig;
                if (c0 > rowg0)     s[ni][0] = -1e30f;
                if (c0 + 1 > rowg0) s[ni][1] = -1e30f;
                if (c0 > rowg1)     s[ni][2] = -1e30f;
                if (c0 + 1 > rowg1) s[ni][3] = -1e30f;
            }
        }

        // Partial row max over this half
        float rmax0 = -1e30f, rmax1 = -1e30f;
#pragma unroll
        for (int ni = 0; ni < 4; ++ni) {
            rmax0 = fmaxf(rmax0, fmaxf(s[ni][0], s[ni][1]));
            rmax1 = fmaxf(rmax1, fmaxf(s[ni][2], s[ni][3]));
        }
        rmax0 = fmaxf(rmax0, __shfl_xor_sync(0xffffffffu, rmax0, 1));
        rmax0 = fmaxf(rmax0, __shfl_xor_sync(0xffffffffu, rmax0, 2));
        rmax1 = fmaxf(rmax1, __shfl_xor_sync(0xffffffffu, rmax1, 1));
        rmax1 = fmaxf(rmax1, __shfl_xor_sync(0xffffffffu, rmax1, 2));
        if (tig == 0) {
            redM[hf * 128 + prow]     = rmax0;
            redM[hf * 128 + prow + 8] = rmax1;
        }
        __syncthreads();
        rmax0 = fmaxf(rmax0, redM[(hf ^ 1) * 128 + prow]);
        rmax1 = fmaxf(rmax1, redM[(hf ^ 1) * 128 + prow + 8]);

        float mn0 = fmaxf(m0, rmax0), mn1 = fmaxf(m1, rmax1);
        float al0 = __expf(m0 - mn0), al1 = __expf(m1 - mn1);
        float rs0 = 0.f, rs1 = 0.f;
#pragma unroll
        for (int ni = 0; ni < 4; ++ni) {
            s[ni][0] = __expf(s[ni][0] - mn0); rs0 += s[ni][0];
            s[ni][1] = __expf(s[ni][1] - mn0); rs0 += s[ni][1];
            s[ni][2] = __expf(s[ni][2] - mn1); rs1 += s[ni][2];
            s[ni][3] = __expf(s[ni][3] - mn1); rs1 += s[ni][3];
        }
        rs0 += __shfl_xor_sync(0xffffffffu, rs0, 1);
        rs0 += __shfl_xor_sync(0xffffffffu, rs0, 2);
        rs1 += __shfl_xor_sync(0xffffffffu, rs1, 1);
        rs1 += __shfl_xor_sync(0xffffffffu, rs1, 2);
        if (tig == 0) {
            redS[hf * 128 + prow]     = rs0;
            redS[hf * 128 + prow + 8] = rs1;
        }
        __syncthreads();
        rs0 += redS[(hf ^ 1) * 128 + prow];
        rs1 += redS[(hf ^ 1) * 128 + prow + 8];
        l0 = l0 * al0 + rs0; m0 = mn0;
        l1 = l1 * al1 + rs1; m1 = mn1;

#pragma unroll
        for (int ni = 0; ni < 16; ++ni) {
            o[ni][0] *= al0; o[ni][1] *= al0;
            o[ni][2] *= al1; o[ni][3] *= al1;
        }

        // P -> smem (warp-private rows x own half cols, tf32)
#pragma unroll
        for (int ni = 0; ni < 4; ++ni) {
            int pc = hf * 32 + ni * 8 + 2 * tig;
            uint2 u0 = { f2tf(s[ni][0]), f2tf(s[ni][1]) };
            uint2 u1 = { f2tf(s[ni][2]), f2tf(s[ni][3]) };
            *(uint2*)&Ps[prow][pc]     = u0;
            *(uint2*)&Ps[prow + 8][pc] = u1;
        }
        __syncwarp();

        // O += P(half) @ V(half rows)
#pragma unroll
        for (int kk = 0; kk < 4; ++kk) {
            const int k0 = hf * 32 + kk * 8;
            unsigned a0 = Ps[prow][k0 + tig];
            unsigned a1 = Ps[prow + 8][k0 + tig];
            unsigned a2 = Ps[prow][k0 + tig + 4];
            unsigned a3 = Ps[prow + 8][k0 + tig + 4];
#pragma unroll
            for (int ni = 0; ni < 16; ++ni) {
                unsigned b0 = Vs[k0 + tig][ni * 8 + gid];
                unsigned b1 = Vs[k0 + tig + 4][ni * 8 + gid];
                mma_tf32(o[ni], a0, a1, a2, a3, b0, b1);
            }
        }
    }

    // Combine partial O across halves (through reused K/V smem), then store.
    __syncthreads();
    float (*ex)[132] = (float(*)[132])Ks;   // 128 x 132 floats fits in Ks+Vs
    if (hf == 1) {
#pragma unroll
        for (int ni = 0; ni < 16; ++ni) {
            int col = ni * 8 + 2 * tig;
            *(float2*)&ex[prow][col]     = *(float2*)&o[ni][0];
            *(float2*)&ex[prow + 8][col] = *(float2*)&o[ni][2];
        }
    }
    __syncthreads();
    if (hf == 0) {
        const float inv0 = 1.f / l0, inv1 = 1.f / l1;
        const int r0 = qt * 128 + ws * 16 + gid;
        float* dst0 = g_ctx + ((size_t)(b * L_ + r0) * H_ + h) * DH_;
        float* dst1 = g_ctx + ((size_t)(b * L_ + r0 + 8) * H_ + h) * DH_;
#pragma unroll
        for (int ni = 0; ni < 16; ++ni) {
            int col = ni * 8 + 2 * tig;
            float2 e0 = *(float2*)&ex[prow][col];
            float2 e1 = *(float2*)&ex[prow + 8][col];
            float2 v0 = { (o[ni][0] + e0.x) * inv0, (o[ni][1] + e0.y) * inv0 };
            float2 v1 = { (o[ni][2] + e1.x) * inv1, (o[ni][3] + e1.y) * inv1 };
            *(float2*)(dst0 + col) = v0;
            *(float2*)(dst1 + col) = v1;
        }
    }
}

// ---------------------------------------------------------------------------
// Launcher
// ---------------------------------------------------------------------------
extern "C" void kernel_launch(void* const* d_in, const int* in_sizes, int n_in,
                              void* d_out, int out_size)
{
    const float* in_q = (const float*)d_in[0];
    const float* in_k = (const float*)d_in[1];
    const float* in_v = (const float*)d_in[2];
    const float* Wq   = (const float*)d_in[3];
    const float* bq   = (const float*)d_in[4];
    const float* Wk   = (const float*)d_in[5];
    const float* bk   = (const float*)d_in[6];
    const float* Wv   = (const float*)d_in[7];
    const float* bv   = (const float*)d_in[8];
    const float* Wo   = (const float*)d_in[9];
    const float* bo   = (const float*)d_in[10];
    const float* qes  = (const float*)d_in[11];
    float* out = (float*)d_out;

    float *pq, *pk, *pv, *pctx;
    cudaGetSymbolAddress((void**)&pq,   g_q);
    cudaGetSymbolAddress((void**)&pk,   g_k);
    cudaGetSymbolAddress((void**)&pv,   g_v);
    cudaGetSymbolAddress((void**)&pctx, g_ctx);

    const int M = B_ * L_;   // 4096

    // Fused Q/K/V projections (640 CTAs)
    gemm3_kernel<<<640, 256>>>(in_q, Wq, bq, pq,
                               in_k, Wk, bk, pk,
                               in_v, Wv, bv, pv);

    const int smem = (16384 + 64 * KP + 64 * VP + 128 * PP + 512) * (int)sizeof(unsigned);
    cudaFuncSetAttribute(flash_tf32_kernel,
                         cudaFuncAttributeMaxDynamicSharedMemorySize, smem);
    flash_tf32_kernel<<<dim3(L_ / 128, B_ * H_), 512, smem>>>(qes);

    gemm_tf32_kernel<<<dim3(D_ / 128, M / 128), 256>>>(
        pctx, Wo, bo, out, M, D_, H_ * DH_);
}

// round 9
// speedup vs baseline: 5.0457x; 1.1202x over previous
#include <cuda_runtime.h>
#include <math.h>

// Problem constants
#define B_   2
#define L_   2048
#define D_   1024
#define H_   16
#define G_   2
#define DH_  128

// Scratch (no cudaMalloc allowed)
__device__ float g_q[(size_t)B_ * L_ * H_ * DH_];
__device__ float g_k[(size_t)B_ * L_ * G_ * DH_];
__device__ float g_v[(size_t)B_ * L_ * G_ * DH_];
__device__ float g_ctx[(size_t)B_ * L_ * H_ * DH_];

__device__ __forceinline__ unsigned f2tf(float x) {
    unsigned r;
    asm("cvt.rna.tf32.f32 %0, %1;" : "=r"(r) : "f"(x));
    return r;
}

__device__ __forceinline__ void mma_tf32(float c[4],
    unsigned a0, unsigned a1, unsigned a2, unsigned a3,
    unsigned b0, unsigned b1)
{
    asm("mma.sync.aligned.m16n8k8.row.col.f32.tf32.tf32.f32 "
        "{%0,%1,%2,%3},{%4,%5,%6,%7},{%8,%9},{%0,%1,%2,%3};"
        : "+f"(c[0]), "+f"(c[1]), "+f"(c[2]), "+f"(c[3])
        : "r"(a0), "r"(a1), "r"(a2), "r"(a3), "r"(b0), "r"(b1));
}

// ---------------------------------------------------------------------------
// TF32 GEMM body with bias, double-buffered: C = A[.,K] @ B[K,N] + bias[N]
// BM=128, BN=128, BK=16, 256 threads (8 warps, 4x2), warp tile 32x64.
// ---------------------------------------------------------------------------
#define APITCH 20
#define BPITCH 136

__device__ __forceinline__ void gemm_body(
    const float* __restrict__ A, const float* __restrict__ Bm,
    const float* __restrict__ bias, float* __restrict__ C,
    int N, int K, int bm, int bn)
{
    __shared__ unsigned As[2][128][APITCH];
    __shared__ unsigned Bs[2][16][BPITCH];

    const int tid  = threadIdx.x;
    const int warp = tid >> 5, lane = tid & 31;
    const int wm = warp >> 1, wn = warp & 1;
    const int gid = lane >> 2, tig = lane & 3;

    float acc[2][8][4];
#pragma unroll
    for (int mi = 0; mi < 2; ++mi)
#pragma unroll
        for (int ni = 0; ni < 8; ++ni)
#pragma unroll
            for (int r = 0; r < 4; ++r) acc[mi][ni][r] = 0.f;

    const int ar = tid >> 2, ac = (tid & 3) << 2;
    const int br = tid >> 5, bc = (tid & 31) << 2;

    float4 ra[2], rb[2];
#pragma unroll
    for (int rr = 0; rr < 2; ++rr)
        ra[rr] = *(const float4*)(A + (size_t)(bm + ar + rr * 64) * K + ac);
#pragma unroll
    for (int rr = 0; rr < 2; ++rr)
        rb[rr] = *(const float4*)(Bm + (size_t)(br + rr * 8) * N + bn + bc);
#pragma unroll
    for (int rr = 0; rr < 2; ++rr) {
        int r = ar + rr * 64;
        As[0][r][ac + 0] = f2tf(ra[rr].x);
        As[0][r][ac + 1] = f2tf(ra[rr].y);
        As[0][r][ac + 2] = f2tf(ra[rr].z);
        As[0][r][ac + 3] = f2tf(ra[rr].w);
        uint4 u = { f2tf(rb[rr].x), f2tf(rb[rr].y), f2tf(rb[rr].z), f2tf(rb[rr].w) };
        *(uint4*)&Bs[0][br + rr * 8][bc] = u;
    }

    int buf = 0;
    for (int kt = 0; kt < K; kt += 16) {
        __syncthreads();
        const bool more = (kt + 16) < K;
        if (more) {
#pragma unroll
            for (int rr = 0; rr < 2; ++rr)
                ra[rr] = *(const float4*)(A + (size_t)(bm + ar + rr * 64) * K + kt + 16 + ac);
#pragma unroll
            for (int rr = 0; rr < 2; ++rr)
                rb[rr] = *(const float4*)(Bm + (size_t)(kt + 16 + br + rr * 8) * N + bn + bc);
        }

#pragma unroll
        for (int kk = 0; kk < 2; ++kk) {
            const int k0 = kk * 8;
            unsigned a[2][4];
#pragma unroll
            for (int mi = 0; mi < 2; ++mi) {
                int row = wm * 32 + mi * 16 + gid;
                a[mi][0] = As[buf][row][k0 + tig];
                a[mi][1] = As[buf][row + 8][k0 + tig];
                a[mi][2] = As[buf][row][k0 + tig + 4];
                a[mi][3] = As[buf][row + 8][k0 + tig + 4];
            }
#pragma unroll
            for (int ni = 0; ni < 8; ++ni) {
                int col = wn * 64 + ni * 8 + gid;
                unsigned b0 = Bs[buf][k0 + tig][col];
                unsigned b1 = Bs[buf][k0 + tig + 4][col];
                mma_tf32(acc[0][ni], a[0][0], a[0][1], a[0][2], a[0][3], b0, b1);
                mma_tf32(acc[1][ni], a[1][0], a[1][1], a[1][2], a[1][3], b0, b1);
            }
        }

        if (more) {
            int nb = buf ^ 1;
#pragma unroll
            for (int rr = 0; rr < 2; ++rr) {
                int r = ar + rr * 64;
                As[nb][r][ac + 0] = f2tf(ra[rr].x);
                As[nb][r][ac + 1] = f2tf(ra[rr].y);
                As[nb][r][ac + 2] = f2tf(ra[rr].z);
                As[nb][r][ac + 3] = f2tf(ra[rr].w);
                uint4 u = { f2tf(rb[rr].x), f2tf(rb[rr].y), f2tf(rb[rr].z), f2tf(rb[rr].w) };
                *(uint4*)&Bs[nb][br + rr * 8][bc] = u;
            }
        }
        buf ^= 1;
    }

#pragma unroll
    for (int mi = 0; mi < 2; ++mi)
#pragma unroll
        for (int ni = 0; ni < 8; ++ni) {
            int row = bm + wm * 32 + mi * 16 + gid;
            int col = bn + wn * 64 + ni * 8 + 2 * tig;
            float bx = bias[col], by = bias[col + 1];
            float2 o0 = { acc[mi][ni][0] + bx, acc[mi][ni][1] + by };
            float2 o1 = { acc[mi][ni][2] + bx, acc[mi][ni][3] + by };
            *(float2*)(C + (size_t)row * N + col) = o0;
            *(float2*)(C + (size_t)(row + 8) * N + col) = o1;
        }
}

// Fused Q/K/V projection: grid.x = 512 + 64 + 64 = 640
__global__ void __launch_bounds__(256, 2) gemm3_kernel(
    const float* __restrict__ in_q, const float* __restrict__ Wq,
    const float* __restrict__ bq, float* __restrict__ pq,
    const float* __restrict__ in_k, const float* __restrict__ Wk,
    const float* __restrict__ bk, float* __restrict__ pk,
    const float* __restrict__ in_v, const float* __restrict__ Wv,
    const float* __restrict__ bv, float* __restrict__ pv)
{
    const int blk = blockIdx.x;
    if (blk < 512) {
        gemm_body(in_q, Wq, bq, pq, 2048, 1024, (blk >> 4) * 128, (blk & 15) * 128);
    } else if (blk < 576) {
        int t = blk - 512;
        gemm_body(in_k, Wk, bk, pk, 256, 1024, (t >> 1) * 128, (t & 1) * 128);
    } else {
        int t = blk - 576;
        gemm_body(in_v, Wv, bv, pv, 256, 1024, (t >> 1) * 128, (t & 1) * 128);
    }
}

__global__ void __launch_bounds__(256, 2) gemm_tf32_kernel(
    const float* __restrict__ A, const float* __restrict__ Bm,
    const float* __restrict__ bias, float* __restrict__ C,
    int M, int N, int K)
{
    gemm_body(A, Bm, bias, C, N, K, blockIdx.y * 128, blockIdx.x * 128);
}

// ---------------------------------------------------------------------------
// TF32 flash attention (causal, GQA). Block: 64 q rows of one head.
// 128 threads = 4 warps; warp w owns q rows w*16..+15 (full 64-wide KV).
// Q kept in registers as prebuilt A-fragments. 2 CTAs/SM co-resident.
// ---------------------------------------------------------------------------
#define KP 132
#define VP 136
#define PP 68

__global__ void __launch_bounds__(128) flash_tf32_kernel(const float* __restrict__ qes)
{
    extern __shared__ unsigned sm[];
    unsigned (*Ks)[KP] = (unsigned(*)[KP])sm;                 // [64][132]
    unsigned (*Vs)[VP] = (unsigned(*)[VP])(sm + 64 * KP);     // [64][136]
    unsigned (*Ps)[PP] = (unsigned(*)[PP])(sm + 64 * KP + 64 * VP); // [64][68]

    const int tid  = threadIdx.x;
    const int warp = tid >> 5, lane = tid & 31;
    const int gid = lane >> 2, tig = lane & 3;
    const int qt = (int)gridDim.x - 1 - (int)blockIdx.x;   // heavy tiles first
    const int bh = blockIdx.y;
    const int b = bh >> 4, h = bh & 15, g = h >> 3;

    const float scale = qes[0] * 0.08838834764831845f;  // qes / sqrt(128)

    const int d0 = (tid & 31) << 2;
    const int j0 = tid >> 5;
    const int prow = warp * 16 + gid;

    // Stage Q tile (scaled, tf32) through Ks, then build A-fragments in regs.
#pragma unroll
    for (int it = 0; it < 16; ++it) {
        int r = j0 + it * 4;
        float4 v = *(const float4*)(g_q +
            ((size_t)(b * L_ + qt * 64 + r) * H_ + h) * DH_ + d0);
        uint4 u = { f2tf(v.x * scale), f2tf(v.y * scale),
                    f2tf(v.z * scale), f2tf(v.w * scale) };
        *(uint4*)&Ks[r][d0] = u;
    }
    __syncthreads();

    unsigned aq[16][4];
#pragma unroll
    for (int kk = 0; kk < 16; ++kk) {
        aq[kk][0] = Ks[prow][kk * 8 + tig];
        aq[kk][1] = Ks[prow + 8][kk * 8 + tig];
        aq[kk][2] = Ks[prow][kk * 8 + tig + 4];
        aq[kk][3] = Ks[prow + 8][kk * 8 + tig + 4];
    }

    float m0 = -1e30f, m1 = -1e30f, l0 = 0.f, l1 = 0.f;
    float o[16][4];
#pragma unroll
    for (int ni = 0; ni < 16; ++ni)
#pragma unroll
        for (int r = 0; r < 4; ++r) o[ni][r] = 0.f;

    const int ntiles = qt + 1;

    for (int t = 0; t < ntiles; ++t) {
        __syncthreads();   // Q-frag reads (t=0) / prev-tile consumers done
        // Load K,V tile gmem -> smem (tf32)
#pragma unroll
        for (int it = 0; it < 16; ++it) {
            int j = j0 + it * 4;
            size_t base = ((size_t)(b * L_ + t * 64 + j) * G_ + g) * DH_ + d0;
            float4 kv = *(const float4*)(g_k + base);
            uint4 uk = { f2tf(kv.x), f2tf(kv.y), f2tf(kv.z), f2tf(kv.w) };
            *(uint4*)&Ks[j][d0] = uk;
            float4 vv = *(const float4*)(g_v + base);
            uint4 uv = { f2tf(vv.x), f2tf(vv.y), f2tf(vv.z), f2tf(vv.w) };
            *(uint4*)&Vs[j][d0] = uv;
        }
        __syncthreads();

        // S = Q @ K^T  (warp rows prow, prow+8; 8 n-tiles of 8)
        float s[8][4];
#pragma unroll
        for (int ni = 0; ni < 8; ++ni)
#pragma unroll
            for (int r = 0; r < 4; ++r) s[ni][r] = 0.f;

#pragma unroll
        for (int kk = 0; kk < 16; ++kk) {
            const int k0 = kk * 8;
#pragma unroll
            for (int ni = 0; ni < 8; ++ni) {
                unsigned b0 = Ks[ni * 8 + gid][k0 + tig];
                unsigned b1 = Ks[ni * 8 + gid][k0 + tig + 4];
                mma_tf32(s[ni], aq[kk][0], aq[kk][1], aq[kk][2], aq[kk][3], b0, b1);
            }
        }

        // Causal mask (diagonal tile only)
        if (t == qt) {
            const int rowg0 = qt * 64 + warp * 16 + gid;
            const int rowg1 = rowg0 + 8;
#pragma unroll
            for (int ni = 0; ni < 8; ++ni) {
                int c0 = t * 64 + ni * 8 + 2 * tig;
                if (c0 > rowg0)     s[ni][0] = -1e30f;
                if (c0 + 1 > rowg0) s[ni][1] = -1e30f;
                if (c0 > rowg1)     s[ni][2] = -1e30f;
                if (c0 + 1 > rowg1) s[ni][3] = -1e30f;
            }
        }

        // Online softmax (full row per warp; reduce over 4-lane groups)
        float rmax0 = -1e30f, rmax1 = -1e30f;
#pragma unroll
        for (int ni = 0; ni < 8; ++ni) {
            rmax0 = fmaxf(rmax0, fmaxf(s[ni][0], s[ni][1]));
            rmax1 = fmaxf(rmax1, fmaxf(s[ni][2], s[ni][3]));
        }
        rmax0 = fmaxf(rmax0, __shfl_xor_sync(0xffffffffu, rmax0, 1));
        rmax0 = fmaxf(rmax0, __shfl_xor_sync(0xffffffffu, rmax0, 2));
        rmax1 = fmaxf(rmax1, __shfl_xor_sync(0xffffffffu, rmax1, 1));
        rmax1 = fmaxf(rmax1, __shfl_xor_sync(0xffffffffu, rmax1, 2));

        float mn0 = fmaxf(m0, rmax0), mn1 = fmaxf(m1, rmax1);
        float al0 = __expf(m0 - mn0), al1 = __expf(m1 - mn1);
        float rs0 = 0.f, rs1 = 0.f;
#pragma unroll
        for (int ni = 0; ni < 8; ++ni) {
            s[ni][0] = __expf(s[ni][0] - mn0); rs0 += s[ni][0];
            s[ni][1] = __expf(s[ni][1] - mn0); rs0 += s[ni][1];
            s[ni][2] = __expf(s[ni][2] - mn1); rs1 += s[ni][2];
            s[ni][3] = __expf(s[ni][3] - mn1); rs1 += s[ni][3];
        }
        rs0 += __shfl_xor_sync(0xffffffffu, rs0, 1);
        rs0 += __shfl_xor_sync(0xffffffffu, rs0, 2);
        rs1 += __shfl_xor_sync(0xffffffffu, rs1, 1);
        rs1 += __shfl_xor_sync(0xffffffffu, rs1, 2);
        l0 = l0 * al0 + rs0; m0 = mn0;
        l1 = l1 * al1 + rs1; m1 = mn1;

#pragma unroll
        for (int ni = 0; ni < 16; ++ni) {
            o[ni][0] *= al0; o[ni][1] *= al0;
            o[ni][2] *= al1; o[ni][3] *= al1;
        }

        // P -> smem (warp-private rows, tf32)
#pragma unroll
        for (int ni = 0; ni < 8; ++ni) {
            int pc = ni * 8 + 2 * tig;
            uint2 u0 = { f2tf(s[ni][0]), f2tf(s[ni][1]) };
            uint2 u1 = { f2tf(s[ni][2]), f2tf(s[ni][3]) };
            *(uint2*)&Ps[prow][pc]     = u0;
            *(uint2*)&Ps[prow + 8][pc] = u1;
        }
        __syncwarp();

        // O += P @ V
#pragma unroll
        for (int kk = 0; kk < 8; ++kk) {
            const int k0 = kk * 8;
            unsigned a0 = Ps[prow][k0 + tig];
            unsigned a1 = Ps[prow + 8][k0 + tig];
            unsigned a2 = Ps[prow][k0 + tig + 4];
            unsigned a3 = Ps[prow + 8][k0 + tig + 4];
#pragma unroll
            for (int ni = 0; ni < 16; ++ni) {
                unsigned b0 = Vs[k0 + tig][ni * 8 + gid];
                unsigned b1 = Vs[k0 + tig + 4][ni * 8 + gid];
                mma_tf32(o[ni], a0, a1, a2, a3, b0, b1);
            }
        }
    }

    // Epilogue: O / l -> g_ctx
    const float inv0 = 1.f / l0, inv1 = 1.f / l1;
    const int r0 = qt * 64 + warp * 16 + gid;
    float* dst0 = g_ctx + ((size_t)(b * L_ + r0) * H_ + h) * DH_;
    float* dst1 = g_ctx + ((size_t)(b * L_ + r0 + 8) * H_ + h) * DH_;
#pragma unroll
    for (int ni = 0; ni < 16; ++ni) {
        int col = ni * 8 + 2 * tig;
        float2 v0 = { o[ni][0] * inv0, o[ni][1] * inv0 };
        float2 v1 = { o[ni][2] * inv1, o[ni][3] * inv1 };
        *(float2*)(dst0 + col) = v0;
        *(float2*)(dst1 + col) = v1;
    }
}

// ---------------------------------------------------------------------------
// Launcher
// ---------------------------------------------------------------------------
extern "C" void kernel_launch(void* const* d_in, const int* in_sizes, int n_in,
                              void* d_out, int out_size)
{
    const float* in_q = (const float*)d_in[0];
    const float* in_k = (const float*)d_in[1];
    const float* in_v = (const float*)d_in[2];
    const float* Wq   = (const float*)d_in[3];
    const float* bq   = (const float*)d_in[4];
    const float* Wk   = (const float*)d_in[5];
    const float* bk   = (const float*)d_in[6];
    const float* Wv   = (const float*)d_in[7];
    const float* bv   = (const float*)d_in[8];
    const float* Wo   = (const float*)d_in[9];
    const float* bo   = (const float*)d_in[10];
    const float* qes  = (const float*)d_in[11];
    float* out = (float*)d_out;

    float *pq, *pk, *pv, *pctx;
    cudaGetSymbolAddress((void**)&pq,   g_q);
    cudaGetSymbolAddress((void**)&pk,   g_k);
    cudaGetSymbolAddress((void**)&pv,   g_v);
    cudaGetSymbolAddress((void**)&pctx, g_ctx);

    const int M = B_ * L_;   // 4096

    // Fused Q/K/V projections (640 CTAs)
    gemm3_kernel<<<640, 256>>>(in_q, Wq, bq, pq,
                               in_k, Wk, bk, pk,
                               in_v, Wv, bv, pv);

    const int smem = (64 * KP + 64 * VP + 64 * PP) * (int)sizeof(unsigned);
    cudaFuncSetAttribute(flash_tf32_kernel,
                         cudaFuncAttributeMaxDynamicSharedMemorySize, smem);
    flash_tf32_kernel<<<dim3(L_ / 64, B_ * H_), 128, smem>>>(qes);

    gemm_tf32_kernel<<<dim3(D_ / 128, M / 128), 256>>>(
        pctx, Wo, bo, out, M, D_, H_ * DH_);
}